// round 2
// baseline (speedup 1.0000x reference)
#include <cuda_runtime.h>
#include <math.h>

// Problem dims
#define VV 32000
#define EE 512
#define HH 1024
#define BB 16
#define TT 256
#define H3 3072
#define MM 4096   // BB*TT

// ---------------- scratch (device globals; no cudaMalloc allowed) ----------------
__device__ float d_xe[MM * EE];          // [t*B+b][E]       8 MB
__device__ float d_gx0[MM * H3];         // [t*B+b][3H]     50 MB
__device__ float d_Wh0T[H3 * HH];        // [j][k]          12.6 MB
__device__ float d_h0seq[MM * HH];       // [t*B+b][H]      16.8 MB
__device__ float d_hinit[BB * HH];       // zeros
__device__ float d_g1x[MM * H3];         // 50 MB
__device__ float d_g1h[MM * H3];         // 50 MB
__device__ float d_h1[MM * HH];          // [b*T+t][H]      16.8 MB

// ---------------- embedding gather: xe[t*B+b][:] = emb[x[b][t]] ----------------
__global__ void gather_embed_k(const int* __restrict__ x,
                               const float* __restrict__ emb) {
    int r = blockIdx.x;              // t*B + b
    int t = r >> 4;
    int b = r & 15;
    int tok = x[b * TT + t];
    const float4* src = (const float4*)(emb + (size_t)tok * EE);
    float4* dst = (float4*)(d_xe + (size_t)r * EE);
    dst[threadIdx.x] = src[threadIdx.x];   // 128 threads * float4 = 512 floats
}

// ---------------- transpose Wh0 [1024,3072] -> Wh0T [3072,1024] ----------------
__global__ void transpose_k(const float* __restrict__ in) {
    __shared__ float tile[32][33];
    int c0 = blockIdx.x * 32;   // col in source (0..3071)
    int r0 = blockIdx.y * 32;   // row in source (0..1023)
    for (int dy = threadIdx.y; dy < 32; dy += 8)
        tile[dy][threadIdx.x] = in[(size_t)(r0 + dy) * H3 + c0 + threadIdx.x];
    __syncthreads();
    for (int dy = threadIdx.y; dy < 32; dy += 8)
        d_Wh0T[(size_t)(c0 + dy) * HH + r0 + threadIdx.x] = tile[threadIdx.x][dy];
}

// ---------------- zero init for h0 at t=-1 ----------------
__global__ void zero_hinit_k() {
    int i = blockIdx.x * 256 + threadIdx.x;
    if (i < BB * HH) d_hinit[i] = 0.f;
}

// ---------------- generic fp32 SGEMM with bias: C[M,N] = A[M,K]@B[K,N] + bias ----------------
// Requires M%128==0, N%128==0, K%16==0. 256 threads, 128x128 tile, 8x8 microtile.
__global__ __launch_bounds__(256) void sgemm_bias_k(
    int M, int N, int K,
    const float* __restrict__ A, const float* __restrict__ B,
    const float* __restrict__ bias, float* __restrict__ C)
{
    __shared__ float As[16][132];   // [k][m], padded
    __shared__ float Bs[16][128];   // [k][n]
    const int tid = threadIdx.x;
    const int tx = tid & 15;        // n dir
    const int ty = tid >> 4;        // m dir
    const int aRow = tid >> 2;      // 0..63
    const int aCol = (tid & 3) << 2;
    const int bRow = tid >> 5;      // 0..7
    const int bCol = (tid & 31) << 2;
    const float* Ab = A + (size_t)blockIdx.y * 128 * K;
    const float* Bb = B + (size_t)blockIdx.x * 128;

    float acc[8][8];
    #pragma unroll
    for (int i = 0; i < 8; i++)
        #pragma unroll
        for (int j = 0; j < 8; j++) acc[i][j] = 0.f;

    for (int k0 = 0; k0 < K; k0 += 16) {
        float4 a0 = *(const float4*)(Ab + (size_t)aRow * K + k0 + aCol);
        float4 a1 = *(const float4*)(Ab + (size_t)(aRow + 64) * K + k0 + aCol);
        As[aCol + 0][aRow] = a0.x; As[aCol + 1][aRow] = a0.y;
        As[aCol + 2][aRow] = a0.z; As[aCol + 3][aRow] = a0.w;
        As[aCol + 0][aRow + 64] = a1.x; As[aCol + 1][aRow + 64] = a1.y;
        As[aCol + 2][aRow + 64] = a1.z; As[aCol + 3][aRow + 64] = a1.w;
        *(float4*)&Bs[bRow][bCol]     = *(const float4*)(Bb + (size_t)(k0 + bRow) * N + bCol);
        *(float4*)&Bs[bRow + 8][bCol] = *(const float4*)(Bb + (size_t)(k0 + bRow + 8) * N + bCol);
        __syncthreads();
        #pragma unroll
        for (int kk = 0; kk < 16; kk++) {
            float ar[8], br[8];
            *(float4*)&ar[0] = *(const float4*)&As[kk][ty * 8];
            *(float4*)&ar[4] = *(const float4*)&As[kk][ty * 8 + 4];
            *(float4*)&br[0] = *(const float4*)&Bs[kk][tx * 8];
            *(float4*)&br[4] = *(const float4*)&Bs[kk][tx * 8 + 4];
            #pragma unroll
            for (int i = 0; i < 8; i++)
                #pragma unroll
                for (int j = 0; j < 8; j++)
                    acc[i][j] = fmaf(ar[i], br[j], acc[i][j]);
        }
        __syncthreads();
    }
    const int col0 = blockIdx.x * 128 + tx * 8;
    #pragma unroll
    for (int i = 0; i < 8; i++) {
        size_t row = (size_t)blockIdx.y * 128 + ty * 8 + i;
        float* Cp = C + row * N + col0;
        #pragma unroll
        for (int j = 0; j < 8; j++)
            Cp[j] = acc[i][j] + bias[col0 + j];
    }
}

// ---------------- sequential GRU layer-0 step ----------------
// grid 128 (8 hidden outputs each), 256 threads = 8 ii * 32 ksplit (chunk 32)
#define STEP_SMEM_BYTES ((16 * 1024 + 3 * 8 * 16 * 33) * 4)

__global__ __launch_bounds__(256) void step_k(int t, const float* __restrict__ bh0)
{
    extern __shared__ float sm[];
    float* h_s = sm;                 // [k][b] : 1024 x 16
    float* red = sm + 16 * 1024;     // [(g*8+ii)*16+b][33]
    const int tid = threadIdx.x;
    const float* hprev = (t == 0) ? d_hinit : (d_h0seq + (size_t)(t - 1) * BB * HH);

    for (int v = tid; v < 4096; v += 256) {
        int b = v >> 8;
        int kq = v & 255;
        float4 hv = *(const float4*)(hprev + b * HH + kq * 4);
        int k = kq * 4;
        h_s[(k + 0) * 16 + b] = hv.x;
        h_s[(k + 1) * 16 + b] = hv.y;
        h_s[(k + 2) * 16 + b] = hv.z;
        h_s[(k + 3) * 16 + b] = hv.w;
    }
    __syncthreads();

    const int ii = tid & 7;
    const int ks = tid >> 3;        // 0..31
    const int i0 = blockIdx.x * 8;
    const float* Wr = d_Wh0T + (size_t)(i0 + ii) * HH;
    const float* Wz = Wr + (size_t)HH * HH;
    const float* Wn = Wz + (size_t)HH * HH;

    float accr[16], accz[16], accn[16];
    #pragma unroll
    for (int b = 0; b < 16; b++) { accr[b] = 0.f; accz[b] = 0.f; accn[b] = 0.f; }

    const int kbase = ks * 32;
    #pragma unroll 2
    for (int k4 = 0; k4 < 8; ++k4) {
        int k = kbase + k4 * 4;
        float4 wr4 = *(const float4*)(Wr + k);
        float4 wz4 = *(const float4*)(Wz + k);
        float4 wn4 = *(const float4*)(Wn + k);
        float wrv[4] = {wr4.x, wr4.y, wr4.z, wr4.w};
        float wzv[4] = {wz4.x, wz4.y, wz4.z, wz4.w};
        float wnv[4] = {wn4.x, wn4.y, wn4.z, wn4.w};
        #pragma unroll
        for (int mm = 0; mm < 4; ++mm) {
            const float* hp = &h_s[(k + mm) * 16];
            float hv[16];
            *(float4*)&hv[0]  = *(const float4*)(hp + 0);
            *(float4*)&hv[4]  = *(const float4*)(hp + 4);
            *(float4*)&hv[8]  = *(const float4*)(hp + 8);
            *(float4*)&hv[12] = *(const float4*)(hp + 12);
            #pragma unroll
            for (int b = 0; b < 16; ++b) {
                accr[b] = fmaf(wrv[mm], hv[b], accr[b]);
                accz[b] = fmaf(wzv[mm], hv[b], accz[b]);
                accn[b] = fmaf(wnv[mm], hv[b], accn[b]);
            }
        }
    }
    #pragma unroll
    for (int b = 0; b < 16; ++b) {
        red[((0 * 8 + ii) * 16 + b) * 33 + ks] = accr[b];
        red[((1 * 8 + ii) * 16 + b) * 33 + ks] = accz[b];
        red[((2 * 8 + ii) * 16 + b) * 33 + ks] = accn[b];
    }
    __syncthreads();

    if (tid < 128) {
        int i2 = tid & 7, b2 = tid >> 3;
        float s[3];
        #pragma unroll
        for (int g = 0; g < 3; ++g) {
            const float* rp = &red[((g * 8 + i2) * 16 + b2) * 33];
            float sum = 0.f;
            #pragma unroll
            for (int q = 0; q < 32; ++q) sum += rp[q];
            s[g] = sum;
        }
        int i = i0 + i2;
        const float* gx = d_gx0 + ((size_t)t * BB + b2) * H3;
        float xr = gx[i], xz = gx[HH + i], xn = gx[2 * HH + i];
        float ghr = s[0] + bh0[i];
        float ghz = s[1] + bh0[HH + i];
        float ghn = s[2] + bh0[2 * HH + i];
        float r = 1.f / (1.f + expf(-(xr + ghr)));
        float z = 1.f / (1.f + expf(-(xz + ghz)));
        float n = tanhf(xn + r * ghn);
        float hold = h_s[i * 16 + b2];
        d_h0seq[((size_t)t * BB + b2) * HH + i] = (1.f - z) * n + z * hold;
    }
}

// ---------------- layer-1 cell math (parallel over all (t,b)) ----------------
__global__ void cell1_k() {
    size_t idx = (size_t)blockIdx.x * 256 + threadIdx.x;  // MM*HH total
    int r = (int)(idx >> 10);   // t*B + b
    int i = (int)(idx & 1023);
    const float* gx = d_g1x + (size_t)r * H3;
    const float* gh = d_g1h + (size_t)r * H3;
    float xr = gx[i], xz = gx[HH + i], xn = gx[2 * HH + i];
    float hr = gh[i], hz = gh[HH + i], hn = gh[2 * HH + i];
    float hp = d_h0seq[idx];    // h0_new is both input and prev hidden (bug reproduced)
    float rr = 1.f / (1.f + expf(-(xr + hr)));
    float z  = 1.f / (1.f + expf(-(xz + hz)));
    float n  = tanhf(xn + rr * hn);
    float h  = (1.f - z) * n + z * hp;
    int t = r >> 4, b = r & 15;
    d_h1[((size_t)b * TT + t) * HH + i] = h;   // [b*T+t][H] for logits GEMM
}

// ---------------- final hidden state [2,B,H] ----------------
__global__ void hidden_k(float* __restrict__ out) {
    int idx = blockIdx.x * 256 + threadIdx.x;   // 0..32767
    int b = (idx >> 10) & 15;
    int i = idx & 1023;
    if (idx < BB * HH)
        out[idx] = d_h0seq[((size_t)(TT - 1) * BB + b) * HH + i];
    else
        out[idx] = d_h1[((size_t)b * TT + (TT - 1)) * HH + i];
}

// ---------------- launch ----------------
extern "C" void kernel_launch(void* const* d_in, const int* in_sizes, int n_in,
                              void* d_out, int out_size) {
    const int*   x   = (const int*)  d_in[0];
    const float* emb = (const float*)d_in[1];
    const float* Wx0 = (const float*)d_in[2];
    const float* Wh0 = (const float*)d_in[3];
    const float* bx0 = (const float*)d_in[4];
    const float* bh0 = (const float*)d_in[5];
    const float* Wx1 = (const float*)d_in[6];
    const float* Wh1 = (const float*)d_in[7];
    const float* bx1 = (const float*)d_in[8];
    const float* bh1 = (const float*)d_in[9];
    const float* fcW = (const float*)d_in[10];
    const float* fcb = (const float*)d_in[11];
    float* out = (float*)d_out;

    // resolve device-global scratch addresses (host side; not an allocation)
    float *p_xe, *p_gx0, *p_h0seq, *p_g1x, *p_g1h, *p_h1;
    cudaGetSymbolAddress((void**)&p_xe,    d_xe);
    cudaGetSymbolAddress((void**)&p_gx0,   d_gx0);
    cudaGetSymbolAddress((void**)&p_h0seq, d_h0seq);
    cudaGetSymbolAddress((void**)&p_g1x,   d_g1x);
    cudaGetSymbolAddress((void**)&p_g1h,   d_g1h);
    cudaGetSymbolAddress((void**)&p_h1,    d_h1);

    cudaFuncSetAttribute(step_k, cudaFuncAttributeMaxDynamicSharedMemorySize,
                         STEP_SMEM_BYTES);

    // Stage A: embed gather + precompute gx0 for all timesteps
    gather_embed_k<<<MM, 128>>>(x, emb);
    transpose_k<<<dim3(H3 / 32, HH / 32), dim3(32, 8)>>>(Wh0);
    zero_hinit_k<<<(BB * HH + 255) / 256, 256>>>();
    sgemm_bias_k<<<dim3(H3 / 128, MM / 128), 256>>>(MM, H3, EE, p_xe, Wx0, bx0, p_gx0);

    // Stage B: sequential layer-0 recurrence
    for (int t = 0; t < TT; ++t)
        step_k<<<128, 256, STEP_SMEM_BYTES>>>(t, bh0);

    // Stage C: layer-1 (fully parallel given h0 sequence)
    sgemm_bias_k<<<dim3(H3 / 128, MM / 128), 256>>>(MM, H3, HH, p_h0seq, Wx1, bx1, p_g1x);
    sgemm_bias_k<<<dim3(H3 / 128, MM / 128), 256>>>(MM, H3, HH, p_h0seq, Wh1, bh1, p_g1h);
    cell1_k<<<(MM * HH) / 256, 256>>>();

    // Stage D: logits = h1 @ fcW + fcb  -> out[0 .. B*T*V)
    sgemm_bias_k<<<dim3(VV / 128, MM / 128), 256>>>(MM, VV, HH, p_h1, fcW, fcb, out);

    // hidden -> out[B*T*V .. )
    hidden_k<<<(2 * BB * HH) / 256, 256>>>(out + (size_t)MM * VV);
}

// round 5
// speedup vs baseline: 1.4091x; 1.4091x over previous
#include <cuda_runtime.h>
#include <cuda_bf16.h>
#include <math.h>

// Problem dims
#define VV 32000
#define EE 512
#define HH 1024
#define BB 16
#define TT 256
#define H3 3072
#define MM 4096   // BB*TT

typedef __nv_bfloat16 bf16;

// ---------------- scratch (device globals; ALL 16B-aligned for vector access) ----------------
__device__ __align__(16) float d_gbuf[MM * H3];    // gx0 (phase A/B), then g1x (phase C)
__device__ __align__(16) float d_g1h[MM * H3];
__device__ __align__(16) float d_Wh0T[H3 * HH];    // [j][k] fp32 for step kernel
__device__ __align__(16) float d_h0seq[MM * HH];   // [t*B+b][H]
__device__ __align__(16) float d_hinit[BB * HH];   // zeros
__device__ __align__(16) float d_h1last[BB * HH];  // final-timestep layer-1 hidden

// bf16 split buffers (hi/lo)
__device__ __align__(16) bf16 d_Wx0T_h[H3 * EE],  d_Wx0T_l[H3 * EE];    // [3H][E]
__device__ __align__(16) bf16 d_Wx1T_h[H3 * HH],  d_Wx1T_l[H3 * HH];    // [3H][H]
__device__ __align__(16) bf16 d_Wh1T_h[H3 * HH],  d_Wh1T_l[H3 * HH];    // [3H][H]
__device__ __align__(16) bf16 d_fcWT_h[(size_t)VV * HH];                // [V][H]
__device__ __align__(16) bf16 d_fcWT_l[(size_t)VV * HH];
__device__ __align__(16) bf16 d_xe_h[MM * EE],    d_xe_l[MM * EE];      // [t*B+b][E]
__device__ __align__(16) bf16 d_h0_h[MM * HH],    d_h0_l[MM * HH];      // [t*B+b][H]
__device__ __align__(16) bf16 d_h1_h[MM * HH],    d_h1_l[MM * HH];      // [b*T+t][H]

// ---------------- split fp32 -> (hi, lo) bf16 ----------------
__device__ __forceinline__ void split_bf16(float x, bf16& h, bf16& l) {
    h = __float2bfloat16(x);
    l = __float2bfloat16(x - __bfloat162float(h));
}

// ---------------- fused embedding gather + split ----------------
// xe_hi/lo[t*B+b][:] = split(emb[x[b][t]])
__global__ void gather_embed_k(const int* __restrict__ x,
                               const float* __restrict__ emb) {
    int r = blockIdx.x;              // t*B + b
    int t = r >> 4;
    int b = r & 15;
    int tok = x[b * TT + t];
    float4 v = ((const float4*)(emb + (size_t)tok * EE))[threadIdx.x];
    bf16 h0, l0, h1, l1, h2, l2, h3, l3;
    split_bf16(v.x, h0, l0); split_bf16(v.y, h1, l1);
    split_bf16(v.z, h2, l2); split_bf16(v.w, h3, l3);
    union { bf16 b[4]; uint2 u; } ph, pl;
    ph.b[0] = h0; ph.b[1] = h1; ph.b[2] = h2; ph.b[3] = h3;
    pl.b[0] = l0; pl.b[1] = l1; pl.b[2] = l2; pl.b[3] = l3;
    size_t o = (size_t)r * EE + threadIdx.x * 4;
    *(uint2*)&d_xe_h[o] = ph.u;
    *(uint2*)&d_xe_l[o] = pl.u;
}

// ---------------- transpose Wh0 [1024,3072] -> Wh0T [3072,1024] (fp32) ----------------
__global__ void transpose_k(const float* __restrict__ in) {
    __shared__ float tile[32][33];
    int c0 = blockIdx.x * 32;
    int r0 = blockIdx.y * 32;
    for (int dy = threadIdx.y; dy < 32; dy += 8)
        tile[dy][threadIdx.x] = in[(size_t)(r0 + dy) * H3 + c0 + threadIdx.x];
    __syncthreads();
    for (int dy = threadIdx.y; dy < 32; dy += 8)
        d_Wh0T[(size_t)(c0 + dy) * HH + r0 + threadIdx.x] = tile[threadIdx.x][dy];
}

__global__ void zero_hinit_k() {
    int i = blockIdx.x * 256 + threadIdx.x;
    if (i < BB * HH) d_hinit[i] = 0.f;
}

// transpose + split: in [K,N] fp32 -> out [N,K] bf16 hi/lo
__global__ void transpose_split_k(const float* __restrict__ in,
                                  bf16* __restrict__ outh, bf16* __restrict__ outl,
                                  int K, int N) {
    __shared__ float tile[32][33];
    int c0 = blockIdx.x * 32;   // N dir
    int r0 = blockIdx.y * 32;   // K dir
    for (int dy = threadIdx.y; dy < 32; dy += 8)
        tile[dy][threadIdx.x] = in[(size_t)(r0 + dy) * N + c0 + threadIdx.x];
    __syncthreads();
    for (int dy = threadIdx.y; dy < 32; dy += 8) {
        bf16 h, l;
        split_bf16(tile[threadIdx.x][dy], h, l);
        size_t o = (size_t)(c0 + dy) * K + r0 + threadIdx.x;
        outh[o] = h; outl[o] = l;
    }
}

// ---------------- split-bf16 tensor-core GEMM ----------------
// C[M,N] = A[M,K] @ B^T[N,K] + bias, fp32 out via 3-product bf16 split.
// 256 threads, block tile 128x128, k-tile 32. Warp grid 2(m) x 4(n), warp tile 64x32.
__device__ __forceinline__ void mma_bf16(float* acc, unsigned a0, unsigned a1,
                                         unsigned a2, unsigned a3,
                                         unsigned b0, unsigned b1) {
    asm volatile(
        "mma.sync.aligned.m16n8k16.row.col.f32.bf16.bf16.f32 "
        "{%0,%1,%2,%3}, {%4,%5,%6,%7}, {%8,%9}, {%0,%1,%2,%3};"
        : "+f"(acc[0]), "+f"(acc[1]), "+f"(acc[2]), "+f"(acc[3])
        : "r"(a0), "r"(a1), "r"(a2), "r"(a3), "r"(b0), "r"(b1));
}

#define SMS 40   // smem row stride (bf16 units) for 32-wide k tile

__global__ __launch_bounds__(256) void gemm_split_k(
    int M, int N, int K,
    const bf16* __restrict__ Ah, const bf16* __restrict__ Al,
    const bf16* __restrict__ Bh, const bf16* __restrict__ Bl,
    const float* __restrict__ bias, float* __restrict__ C)
{
    __shared__ __align__(16) bf16 sAh[128 * SMS], sAl[128 * SMS];
    __shared__ __align__(16) bf16 sBh[128 * SMS], sBl[128 * SMS];

    const int tid  = threadIdx.x;
    const int lane = tid & 31;
    const int wid  = tid >> 5;
    const int wm   = wid >> 2;      // 0..1
    const int wn   = wid & 3;       // 0..3
    const int m0   = blockIdx.x * 128;
    const int n0   = blockIdx.y * 128;

    const int r  = lane >> 2;       // 0..7
    const int cc = (lane & 3) * 2;  // 0,2,4,6

    float acc[4][4][4];
    #pragma unroll
    for (int i = 0; i < 4; i++)
        #pragma unroll
        for (int j = 0; j < 4; j++)
            #pragma unroll
            for (int q = 0; q < 4; q++) acc[i][j][q] = 0.f;

    for (int k0 = 0; k0 < K; k0 += 32) {
        // load 4 tiles (128 x 32 bf16 each): 512 16B-chunks per tile, 2/thread
        #pragma unroll
        for (int i = 0; i < 2; i++) {
            int c   = tid + i * 256;
            int row = c >> 2;
            int seg = (c & 3) * 8;
            size_t ga = (size_t)(m0 + row) * K + k0 + seg;
            size_t gb = (size_t)(n0 + row) * K + k0 + seg;
            *(uint4*)&sAh[row * SMS + seg] = *(const uint4*)(Ah + ga);
            *(uint4*)&sAl[row * SMS + seg] = *(const uint4*)(Al + ga);
            *(uint4*)&sBh[row * SMS + seg] = *(const uint4*)(Bh + gb);
            *(uint4*)&sBl[row * SMS + seg] = *(const uint4*)(Bl + gb);
        }
        __syncthreads();

        #pragma unroll
        for (int ks = 0; ks < 32; ks += 16) {
            unsigned af[4][4], bh[4][2], bl[4][2];
            #pragma unroll
            for (int im = 0; im < 4; im++) {
                int rb = (wm * 64 + im * 16 + r) * SMS + ks + cc;
                af[im][0] = *(const unsigned*)&sAh[rb];
                af[im][1] = *(const unsigned*)&sAh[rb + 8 * SMS];
                af[im][2] = *(const unsigned*)&sAh[rb + 8];
                af[im][3] = *(const unsigned*)&sAh[rb + 8 * SMS + 8];
            }
            #pragma unroll
            for (int in = 0; in < 4; in++) {
                int nb = (wn * 32 + in * 8 + r) * SMS + ks + cc;
                bh[in][0] = *(const unsigned*)&sBh[nb];
                bh[in][1] = *(const unsigned*)&sBh[nb + 8];
                bl[in][0] = *(const unsigned*)&sBl[nb];
                bl[in][1] = *(const unsigned*)&sBl[nb + 8];
            }
            // pass 1: Ahi*Bhi ; pass 2: Ahi*Blo
            #pragma unroll
            for (int im = 0; im < 4; im++)
                #pragma unroll
                for (int in = 0; in < 4; in++) {
                    mma_bf16(acc[im][in], af[im][0], af[im][1], af[im][2], af[im][3],
                             bh[in][0], bh[in][1]);
                    mma_bf16(acc[im][in], af[im][0], af[im][1], af[im][2], af[im][3],
                             bl[in][0], bl[in][1]);
                }
            // pass 3: Alo*Bhi
            #pragma unroll
            for (int im = 0; im < 4; im++) {
                int rb = (wm * 64 + im * 16 + r) * SMS + ks + cc;
                af[im][0] = *(const unsigned*)&sAl[rb];
                af[im][1] = *(const unsigned*)&sAl[rb + 8 * SMS];
                af[im][2] = *(const unsigned*)&sAl[rb + 8];
                af[im][3] = *(const unsigned*)&sAl[rb + 8 * SMS + 8];
            }
            #pragma unroll
            for (int im = 0; im < 4; im++)
                #pragma unroll
                for (int in = 0; in < 4; in++)
                    mma_bf16(acc[im][in], af[im][0], af[im][1], af[im][2], af[im][3],
                             bh[in][0], bh[in][1]);
        }
        __syncthreads();
    }

    // epilogue: c0:(m,n) c1:(m,n+1) c2:(m+8,n) c3:(m+8,n+1)
    #pragma unroll
    for (int im = 0; im < 4; im++) {
        int m = m0 + wm * 64 + im * 16 + r;
        #pragma unroll
        for (int in = 0; in < 4; in++) {
            int n = n0 + wn * 32 + in * 8 + cc;
            float2 bv = *(const float2*)(bias + n);
            float2 v0 = make_float2(acc[im][in][0] + bv.x, acc[im][in][1] + bv.y);
            float2 v1 = make_float2(acc[im][in][2] + bv.x, acc[im][in][3] + bv.y);
            *(float2*)&C[(size_t)m * N + n]       = v0;
            *(float2*)&C[(size_t)(m + 8) * N + n] = v1;
        }
    }
}

// ---------------- sequential GRU layer-0 step (epilogue also emits bf16 hi/lo) ----------------
#define STEP_SMEM_BYTES ((16 * 1024 + 3 * 8 * 16 * 33) * 4)

__global__ __launch_bounds__(256) void step_k(int t, const float* __restrict__ bh0)
{
    extern __shared__ float sm[];
    float* h_s = sm;                 // [k][b] : 1024 x 16
    float* red = sm + 16 * 1024;
    const int tid = threadIdx.x;
    const float* hprev = (t == 0) ? d_hinit : (d_h0seq + (size_t)(t - 1) * BB * HH);

    for (int v = tid; v < 4096; v += 256) {
        int b = v >> 8;
        int kq = v & 255;
        float4 hv = *(const float4*)(hprev + b * HH + kq * 4);
        int k = kq * 4;
        h_s[(k + 0) * 16 + b] = hv.x;
        h_s[(k + 1) * 16 + b] = hv.y;
        h_s[(k + 2) * 16 + b] = hv.z;
        h_s[(k + 3) * 16 + b] = hv.w;
    }
    __syncthreads();

    const int ii = tid & 7;
    const int ks = tid >> 3;
    const int i0 = blockIdx.x * 8;
    const float* Wr = d_Wh0T + (size_t)(i0 + ii) * HH;
    const float* Wz = Wr + (size_t)HH * HH;
    const float* Wn = Wz + (size_t)HH * HH;

    float accr[16], accz[16], accn[16];
    #pragma unroll
    for (int b = 0; b < 16; b++) { accr[b] = 0.f; accz[b] = 0.f; accn[b] = 0.f; }

    const int kbase = ks * 32;
    #pragma unroll 2
    for (int k4 = 0; k4 < 8; ++k4) {
        int k = kbase + k4 * 4;
        float4 wr4 = *(const float4*)(Wr + k);
        float4 wz4 = *(const float4*)(Wz + k);
        float4 wn4 = *(const float4*)(Wn + k);
        float wrv[4] = {wr4.x, wr4.y, wr4.z, wr4.w};
        float wzv[4] = {wz4.x, wz4.y, wz4.z, wz4.w};
        float wnv[4] = {wn4.x, wn4.y, wn4.z, wn4.w};
        #pragma unroll
        for (int mm = 0; mm < 4; ++mm) {
            const float* hp = &h_s[(k + mm) * 16];
            float hv[16];
            *(float4*)&hv[0]  = *(const float4*)(hp + 0);
            *(float4*)&hv[4]  = *(const float4*)(hp + 4);
            *(float4*)&hv[8]  = *(const float4*)(hp + 8);
            *(float4*)&hv[12] = *(const float4*)(hp + 12);
            #pragma unroll
            for (int b = 0; b < 16; ++b) {
                accr[b] = fmaf(wrv[mm], hv[b], accr[b]);
                accz[b] = fmaf(wzv[mm], hv[b], accz[b]);
                accn[b] = fmaf(wnv[mm], hv[b], accn[b]);
            }
        }
    }
    #pragma unroll
    for (int b = 0; b < 16; ++b) {
        red[((0 * 8 + ii) * 16 + b) * 33 + ks] = accr[b];
        red[((1 * 8 + ii) * 16 + b) * 33 + ks] = accz[b];
        red[((2 * 8 + ii) * 16 + b) * 33 + ks] = accn[b];
    }
    __syncthreads();

    if (tid < 128) {
        int i2 = tid & 7, b2 = tid >> 3;
        float s[3];
        #pragma unroll
        for (int g = 0; g < 3; ++g) {
            const float* rp = &red[((g * 8 + i2) * 16 + b2) * 33];
            float sum = 0.f;
            #pragma unroll
            for (int q = 0; q < 32; ++q) sum += rp[q];
            s[g] = sum;
        }
        int i = i0 + i2;
        const float* gx = d_gbuf + ((size_t)t * BB + b2) * H3;   // gx0
        float xr = gx[i], xz = gx[HH + i], xn = gx[2 * HH + i];
        float ghr = s[0] + bh0[i];
        float ghz = s[1] + bh0[HH + i];
        float ghn = s[2] + bh0[2 * HH + i];
        float rr = 1.f / (1.f + expf(-(xr + ghr)));
        float z = 1.f / (1.f + expf(-(xz + ghz)));
        float n = tanhf(xn + rr * ghn);
        float hold = h_s[i * 16 + b2];
        float hnew = (1.f - z) * n + z * hold;
        size_t o = ((size_t)t * BB + b2) * HH + i;
        d_h0seq[o] = hnew;
        bf16 hh, hl;
        split_bf16(hnew, hh, hl);
        d_h0_h[o] = hh;
        d_h0_l[o] = hl;
    }
}

// ---------------- layer-1 cell math (emits bf16 hi/lo + final-step fp32) ----------------
__global__ void cell1_k() {
    size_t idx = (size_t)blockIdx.x * 256 + threadIdx.x;
    int rr = (int)(idx >> 10);   // t*B + b
    int i = (int)(idx & 1023);
    const float* gx = d_gbuf + (size_t)rr * H3;   // g1x
    const float* gh = d_g1h + (size_t)rr * H3;
    float xr = gx[i], xz = gx[HH + i], xn = gx[2 * HH + i];
    float hr = gh[i], hz = gh[HH + i], hn = gh[2 * HH + i];
    float hp = d_h0seq[idx];
    float r = 1.f / (1.f + expf(-(xr + hr)));
    float z = 1.f / (1.f + expf(-(xz + hz)));
    float n = tanhf(xn + r * hn);
    float h = (1.f - z) * n + z * hp;
    int t = rr >> 4, b = rr & 15;
    size_t o = ((size_t)b * TT + t) * HH + i;     // [b*T+t][H] for logits GEMM
    bf16 hh, hl;
    split_bf16(h, hh, hl);
    d_h1_h[o] = hh;
    d_h1_l[o] = hl;
    if (t == TT - 1) d_h1last[b * HH + i] = h;
}

// ---------------- final hidden state [2,B,H] ----------------
__global__ void hidden_k(float* __restrict__ out) {
    int idx = blockIdx.x * 256 + threadIdx.x;
    int b = (idx >> 10) & 15;
    int i = idx & 1023;
    if (idx < BB * HH)
        out[idx] = d_h0seq[((size_t)(TT - 1) * BB + b) * HH + i];
    else
        out[idx] = d_h1last[b * HH + i];
}

// ---------------- launch ----------------
extern "C" void kernel_launch(void* const* d_in, const int* in_sizes, int n_in,
                              void* d_out, int out_size) {
    const int*   x   = (const int*)  d_in[0];
    const float* emb = (const float*)d_in[1];
    const float* Wx0 = (const float*)d_in[2];
    const float* Wh0 = (const float*)d_in[3];
    const float* bx0 = (const float*)d_in[4];
    const float* bh0 = (const float*)d_in[5];
    const float* Wx1 = (const float*)d_in[6];
    const float* Wh1 = (const float*)d_in[7];
    const float* bx1 = (const float*)d_in[8];
    const float* bh1 = (const float*)d_in[9];
    const float* fcW = (const float*)d_in[10];
    const float* fcb = (const float*)d_in[11];
    float* out = (float*)d_out;

    float *p_gbuf, *p_g1h;
    cudaGetSymbolAddress((void**)&p_gbuf, d_gbuf);
    cudaGetSymbolAddress((void**)&p_g1h,  d_g1h);

    bf16 *pWx0h, *pWx0l, *pWx1h, *pWx1l, *pWh1h, *pWh1l, *pfch, *pfcl;
    bf16 *pxeh, *pxel, *ph0h, *ph0l, *ph1h, *ph1l;
    cudaGetSymbolAddress((void**)&pWx0h, d_Wx0T_h);
    cudaGetSymbolAddress((void**)&pWx0l, d_Wx0T_l);
    cudaGetSymbolAddress((void**)&pWx1h, d_Wx1T_h);
    cudaGetSymbolAddress((void**)&pWx1l, d_Wx1T_l);
    cudaGetSymbolAddress((void**)&pWh1h, d_Wh1T_h);
    cudaGetSymbolAddress((void**)&pWh1l, d_Wh1T_l);
    cudaGetSymbolAddress((void**)&pfch,  d_fcWT_h);
    cudaGetSymbolAddress((void**)&pfcl,  d_fcWT_l);
    cudaGetSymbolAddress((void**)&pxeh,  d_xe_h);
    cudaGetSymbolAddress((void**)&pxel,  d_xe_l);
    cudaGetSymbolAddress((void**)&ph0h,  d_h0_h);
    cudaGetSymbolAddress((void**)&ph0l,  d_h0_l);
    cudaGetSymbolAddress((void**)&ph1h,  d_h1_h);
    cudaGetSymbolAddress((void**)&ph1l,  d_h1_l);

    cudaFuncSetAttribute(step_k, cudaFuncAttributeMaxDynamicSharedMemorySize,
                         STEP_SMEM_BYTES);

    dim3 tb(32, 8);

    // Stage A: gather + weight prep
    gather_embed_k<<<MM, 128>>>(x, emb);
    transpose_k<<<dim3(H3 / 32, HH / 32), tb>>>(Wh0);
    zero_hinit_k<<<(BB * HH + 255) / 256, 256>>>();
    transpose_split_k<<<dim3(H3 / 32, EE / 32), tb>>>(Wx0, pWx0h, pWx0l, EE, H3);
    transpose_split_k<<<dim3(H3 / 32, HH / 32), tb>>>(Wx1, pWx1h, pWx1l, HH, H3);
    transpose_split_k<<<dim3(H3 / 32, HH / 32), tb>>>(Wh1, pWh1h, pWh1l, HH, H3);
    transpose_split_k<<<dim3(VV / 32, HH / 32), tb>>>(fcW, pfch, pfcl, HH, VV);

    // gx0 = xe @ Wx0^T-layout + bx0   (into d_gbuf)
    gemm_split_k<<<dim3(MM / 128, H3 / 128), 256>>>(MM, H3, EE, pxeh, pxel,
                                                    pWx0h, pWx0l, bx0, p_gbuf);

    // Stage B: sequential layer-0 recurrence (also emits h0 bf16 hi/lo)
    for (int t = 0; t < TT; ++t)
        step_k<<<128, 256, STEP_SMEM_BYTES>>>(t, bh0);

    // Stage C: layer-1 (g1x reuses d_gbuf; gx0 is dead now)
    gemm_split_k<<<dim3(MM / 128, H3 / 128), 256>>>(MM, H3, HH, ph0h, ph0l,
                                                    pWx1h, pWx1l, bx1, p_gbuf);
    gemm_split_k<<<dim3(MM / 128, H3 / 128), 256>>>(MM, H3, HH, ph0h, ph0l,
                                                    pWh1h, pWh1l, bh1, p_g1h);
    cell1_k<<<(MM * HH) / 256, 256>>>();

    // Stage D: logits = h1 @ fcW + fcb
    gemm_split_k<<<dim3(MM / 128, VV / 128), 256>>>(MM, VV, HH, ph1h, ph1l,
                                                    pfch, pfcl, fcb, out);

    hidden_k<<<(2 * BB * HH) / 256, 256>>>(out + (size_t)MM * VV);
}